// round 14
// baseline (speedup 1.0000x reference)
#include <cuda_runtime.h>
#include <cuda_bf16.h>
#include <cstdint>

#define NNODE 131072
#define NEDGE 2097152
#define BATCH 64
#define NPG   2048
#define KDIM  20480   // N * CS
#define HID   512
#define NPAD  (NEDGE + 3 * NNODE)   // 2490368 padded slots
#define NQUAD (NPAD / 4)            // 622592
#define QPW   8
#define XSTR  32

#define FLAG_A 0x40000000u
#define FLAG_P 0x80000000u
#define VMASK  0x3FFFFFFFu

// fc1 mma.sync config (Karatsuba: 3 real products)
#define FC1_KS    32
#define FC1_KBLK  640
#define FC1_KCH   32
#define FC1_NCH   20
#define SA        40
#define OFF_WRH   0
#define OFF_WRL   5120
#define OFF_WIH   10240
#define OFF_WIL   15360
#define OFF_WSH   20480
#define OFF_WSL   25600
#define OFF_ZRH   30720
#define OFF_ZRL   33280
#define OFF_ZIH   35840
#define OFF_ZIL   38400
#define OFF_ZSH   40960
#define OFF_ZSL   43520
#define FC1_SMEM_BYTES  (46080 * 2)   // 92160

// ---------------- scratch ----------------
__device__ __align__(16) double g_dd[NNODE];        // zeroed by PREVIOUS call's k_head
__device__ __align__(16) float g_deg[NNODE];
__device__ __align__(16) int   g_cursor[NNODE];
__device__ unsigned int g_state[512];
__device__ __align__(16) int2  g_ecw[NPAD];
__device__ __align__(16) int   g_trow[NQUAD];
__device__ __align__(128) float g_T0[NNODE * XSTR];
__device__ __align__(128) float g_B1[NNODE * XSTR];
__device__ __align__(128) float g_B2[NNODE * XSTR];
__device__ __align__(16) float g_zr[BATCH * KDIM];
__device__ __align__(16) float g_zi[BATCH * KDIM];
__device__ __align__(16) float g_accU[2 * BATCH * HID];

// ---------------- helpers ----------------
__device__ __forceinline__ void red4(float* p, float a, float b, float c, float d) {
    asm volatile("red.global.add.v4.f32 [%0], {%1,%2,%3,%4};"
                 :: "l"(p), "f"(a), "f"(b), "f"(c), "f"(d));
}
__device__ __forceinline__ void mma16816(float* d, const uint32_t* a, const uint32_t* b) {
    asm volatile("mma.sync.aligned.m16n8k16.row.col.f32.bf16.bf16.f32 "
                 "{%0,%1,%2,%3}, {%4,%5,%6,%7}, {%8,%9}, {%0,%1,%2,%3};"
                 : "+f"(d[0]), "+f"(d[1]), "+f"(d[2]), "+f"(d[3])
                 : "r"(a[0]), "r"(a[1]), "r"(a[2]), "r"(a[3]), "r"(b[0]), "r"(b[1]));
}
__device__ __forceinline__ void cvt_pair2(float a, float b, uint32_t& hi, uint32_t& lo) {
    uint32_t h;
    asm("cvt.rn.bf16x2.f32 %0, %1, %2;" : "=r"(h) : "f"(b), "f"(a));
    float fa = __uint_as_float(h << 16);
    float fb = __uint_as_float(h & 0xFFFF0000u);
    float la = a - fa, lb = b - fb;
    uint32_t l;
    asm("cvt.rn.bf16x2.f32 %0, %1, %2;" : "=r"(l) : "f"(lb), "f"(la));
    hi = h; lo = l;
}
__device__ __forceinline__ void warp_flush(float* S, int rcur, float4 acc, int lane) {
    acc.x += __shfl_xor_sync(0xffffffffu, acc.x, 8);
    acc.y += __shfl_xor_sync(0xffffffffu, acc.y, 8);
    acc.z += __shfl_xor_sync(0xffffffffu, acc.z, 8);
    acc.w += __shfl_xor_sync(0xffffffffu, acc.w, 8);
    acc.x += __shfl_xor_sync(0xffffffffu, acc.x, 16);
    acc.y += __shfl_xor_sync(0xffffffffu, acc.y, 16);
    acc.z += __shfl_xor_sync(0xffffffffu, acc.z, 16);
    acc.w += __shfl_xor_sync(0xffffffffu, acc.w, 16);
    if (lane < 5) red4(S + rcur * XSTR + lane * 4, acc.x, acc.y, acc.z, acc.w);
}

// ---------------- 1: fused conv1 + degcnt + meta-zero ----------------
__global__ __launch_bounds__(256) void k_convdeg(const float* __restrict__ xr,
                                                 const float* __restrict__ xi,
                                                 const float* __restrict__ wr,
                                                 const float* __restrict__ wi,
                                                 const float* __restrict__ br,
                                                 const float* __restrict__ bi,
                                                 const int* __restrict__ row,
                                                 const float* __restrict__ ew) {
    __shared__ float swr[100], swi[100], sbr[10], sbi[10];
    int t = threadIdx.x;
    int bid = blockIdx.x;
    int e = bid * 256 + t;
    if (bid < 512) {
        if (t < 100) { swr[t] = wr[t]; swi[t] = wi[t]; }
        if (t < 10)  { sbr[t] = br[t]; sbi[t] = bi[t]; }
    }
    if (e < NPAD / 2) ((int4*)g_ecw)[e] = make_int4(0, 0, 0, 0);
    if (e < NQUAD) g_trow[e] = e & (NNODE - 1);
    if (e < 512) g_state[e] = 0u;
    if (e < 2 * BATCH * HID) g_accU[e] = 0.f;
    atomicAdd(&g_dd[row[e]], 1048576.0 + (double)ew[e]);

    if (bid < 512) {
        __syncthreads();
        int n = e;
        float a[10], b_[10];
#pragma unroll
        for (int k = 0; k < 10; k++) { a[k] = xr[n * 10 + k]; b_[k] = xi[n * 10 + k]; }
        float* o = g_T0 + n * XSTR;
#pragma unroll
        for (int c = 0; c < 10; c++) {
            float yr = sbr[c], yi = sbi[c];
#pragma unroll
            for (int k = 0; k < 10; k++) {
                yr += a[k] * swr[c * 10 + k] - b_[k] * swi[c * 10 + k];
                yi += a[k] * swi[c * 10 + k] + b_[k] * swr[c * 10 + k];
            }
            o[c]      = fmaxf(yr, 0.f);
            o[10 + c] = fmaxf(yi, 0.f);
        }
        float4 z4 = make_float4(0.f, 0.f, 0.f, 0.f);
        float4* b1 = (float4*)(g_B1 + n * XSTR);
        float4* b2 = (float4*)(g_B2 + n * XSTR);
#pragma unroll
        for (int j = 0; j < 5; j++) { b1[j] = z4; b2[j] = z4; }
    }
}

// ---------------- 2: single-pass scan (decoupled lookback) + dinv + cursor ----------------
__global__ __launch_bounds__(256) void k_scan() {
    __shared__ int s[256];
    __shared__ int sprefix;
    int t = threadIdx.x, b = blockIdx.x, i = b * 256 + t;
    double dv = g_dd[i];
    int cnt = (int)(dv * 9.5367431640625e-7);
    int v = (cnt + 3) & ~3;
    s[t] = v;
    __syncthreads();
#pragma unroll
    for (int off = 1; off < 256; off <<= 1) {
        int a = (t >= off) ? s[t - off] : 0;
        __syncthreads();
        s[t] += a;
        __syncthreads();
    }
    int incl = s[t];
    if (b == 0) {
        if (t == 255) {
            atomicExch(&g_state[0], FLAG_P | (unsigned)incl);
            sprefix = 0;
        }
    } else if (t >= 224) {
        int lane = t & 31;
        if (lane == 31) atomicExch(&g_state[b], FLAG_A | (unsigned)incl);
        __syncwarp();
        int sum = 0, j0 = b - 1, done = 0;
        while (!done) {
            int j = j0 - lane;
            unsigned st = FLAG_P;
            if (j >= 0) {
                do { st = atomicAdd(&g_state[j], 0u); } while (st == 0u);
            }
            unsigned pm = __ballot_sync(0xffffffffu, (st & FLAG_P) != 0u);
            if (pm == 0u) {
                int val = (int)(st & VMASK);
#pragma unroll
                for (int o = 16; o; o >>= 1) val += __shfl_xor_sync(0xffffffffu, val, o);
                sum += val;
                j0 -= 32;
            } else {
                int pl = __ffs(pm) - 1;
                int val = (lane <= pl) ? (int)(st & VMASK) : 0;
#pragma unroll
                for (int o = 16; o; o >>= 1) val += __shfl_xor_sync(0xffffffffu, val, o);
                sum += val;
                done = 1;
            }
        }
        if (lane == 31) {
            atomicExch(&g_state[b], FLAG_P | (unsigned)(sum + incl));
            sprefix = sum;
        }
    }
    __syncthreads();
    int rs = incl - v + sprefix;
    g_cursor[i] = rs;
    double se = dv - (double)cnt * 1048576.0;
    g_deg[i] = (cnt > 0) ? rsqrtf((float)se + 1e-6f) : 0.f;
}

// ---------------- 3: CSR fill ----------------
__global__ void k_fill(const int* __restrict__ row, const int* __restrict__ col,
                       const float* __restrict__ ew) {
    int e = blockIdx.x * 256 + threadIdx.x;
    int r = row[e], c = col[e];
    float w = ew[e] * g_deg[r] * g_deg[c];
    int pos = atomicAdd(&g_cursor[r], 1);
    g_ecw[pos] = make_int2(c, __float_as_int(w));
    if (!(pos & 3)) g_trow[pos >> 2] = r;
}

// ---------------- 4/5: cooperative 8-lane gather, QPW=8, two-wave, 5 blocks/SM ----------------
__global__ __launch_bounds__(256, 5) void k_gather(int phase) {
    const float* __restrict__ X = (phase == 0) ? g_T0 : g_B1;
    float* S = (phase == 0) ? g_B1 : g_B2;
    int warpId = (blockIdx.x * 256 + threadIdx.x) >> 5;
    int lane = threadIdx.x & 31;
    int eSub = lane >> 3;
    int j = lane & 7;
    int q0 = warpId * QPW;

    int4 r03 = ((const int4*)g_trow)[q0 >> 2];
    int4 r47 = ((const int4*)g_trow)[(q0 >> 2) + 1];

    // wave A: meta + data (MLP=4)
    int2 mA[4];
#pragma unroll
    for (int k = 0; k < 4; k++) mA[k] = g_ecw[(q0 + k) * 4 + eSub];
    float4 v[4];
#pragma unroll
    for (int k = 0; k < 4; k++) {
        float4 tv = make_float4(0.f, 0.f, 0.f, 0.f);
        if (j < 5) tv = ((const float4*)X)[mA[k].x * 8 + j];
        v[k] = tv;
    }
    // wave B meta issued early (independent)
    int2 mB[4];
#pragma unroll
    for (int k = 0; k < 4; k++) mB[k] = g_ecw[(q0 + 4 + k) * 4 + eSub];

    int rA[4] = {r03.x, r03.y, r03.z, r03.w};
    int rB[4] = {r47.x, r47.y, r47.z, r47.w};

    float4 acc = make_float4(0.f, 0.f, 0.f, 0.f);
    int rcur = rA[0];
#pragma unroll
    for (int k = 0; k < 4; k++) {
        if (rA[k] != rcur) {   // warp-uniform
            warp_flush(S, rcur, acc, lane);
            acc = make_float4(0.f, 0.f, 0.f, 0.f);
            rcur = rA[k];
        }
        float w = __int_as_float(mA[k].y);
        acc.x += w * v[k].x;
        acc.y += w * v[k].y;
        acc.z += w * v[k].z;
        acc.w += w * v[k].w;
    }
    // wave B data: reuse v registers
#pragma unroll
    for (int k = 0; k < 4; k++) {
        float4 tv = make_float4(0.f, 0.f, 0.f, 0.f);
        if (j < 5) tv = ((const float4*)X)[mB[k].x * 8 + j];
        v[k] = tv;
    }
#pragma unroll
    for (int k = 0; k < 4; k++) {
        if (rB[k] != rcur) {
            warp_flush(S, rcur, acc, lane);
            acc = make_float4(0.f, 0.f, 0.f, 0.f);
            rcur = rB[k];
        }
        float w = __int_as_float(mB[k].y);
        acc.x += w * v[k].x;
        acc.y += w * v[k].y;
        acc.z += w * v[k].z;
        acc.w += w * v[k].w;
    }
    warp_flush(S, rcur, acc, lane);
}

// ---------------- 6: cheb combine ----------------
__global__ __launch_bounds__(256) void k_cheb(const float* __restrict__ cw,
                                              const float* __restrict__ cb) {
    __shared__ float scw[300], scb[10];
    int t = threadIdx.x;
    for (int i = t; i < 300; i += 256) scw[i] = cw[i];
    if (t < 10) scb[t] = cb[t];
    __syncthreads();
    int n = blockIdx.x * 256 + t;
    float t0[20], t1[20], t2[20];
#pragma unroll
    for (int j = 0; j < 20; j++) {
        float x0 = g_T0[n * XSTR + j];
        float s1 = g_B1[n * XSTR + j];
        float g2 = g_B2[n * XSTR + j];
        t0[j] = x0;
        t1[j] = x0 - s1;
        t2[j] = x0 - 4.f * s1 + 2.f * g2;
    }
    int b = n >> 11;
    int nl = n & (NPG - 1);
    int base = b * KDIM + nl * 10;
#pragma unroll
    for (int o = 0; o < 10; o++) {
        float ar = scb[o], ai = 0.f;
#pragma unroll
        for (int i2 = 0; i2 < 10; i2++) {
            float w0 = scw[i2 * 10 + o], w1 = scw[100 + i2 * 10 + o], w2 = scw[200 + i2 * 10 + o];
            ar += t0[i2] * w0 + t1[i2] * w1 + t2[i2] * w2;
            ai += t0[10 + i2] * w0 + t1[10 + i2] * w1 + t2[10 + i2] * w2;
        }
        g_zr[base + o] = fmaxf(ar, 0.f);
        g_zi[base + o] = fmaxf(ai, 0.f);
    }
}

// ---------------- 7: fc1 complex GEMM — Karatsuba split-bf16 mma.sync ----------------
__global__ __launch_bounds__(256, 1) void k_fc1_mma(const float* __restrict__ Wr,
                                                    const float* __restrict__ Wi) {
    extern __shared__ __align__(16) __nv_bfloat16 sm[];
    const int t = threadIdx.x;
    const int wid = t >> 5, lane = t & 31;
    const int q = lane & 3, rl = lane >> 2;
    const int h0 = blockIdx.x * 128;
    const int kb0 = blockIdx.y * FC1_KBLK;

    const int rowA = t >> 1;
    const int segA = (t & 1) * 16;
    const int rowZ = t >> 1;
    const int segZ = (t & 1) * 16;

    float P1[8][4], P2[8][4], P3[8][4];
#pragma unroll
    for (int n = 0; n < 8; n++)
#pragma unroll
        for (int j = 0; j < 4; j++) { P1[n][j] = 0.f; P2[n][j] = 0.f; P3[n][j] = 0.f; }

    for (int c = 0; c < FC1_NCH; c++) {
        const int kb = kb0 + c * FC1_KCH;
        float fwr[16], fwi[16], fzr[16], fzi[16];
        {
            const float4* p = (const float4*)(Wr + rowA * KDIM + h0 * KDIM + kb + segA);
#pragma unroll
            for (int j = 0; j < 4; j++) {
                float4 v = p[j];
                fwr[4 * j] = v.x; fwr[4 * j + 1] = v.y; fwr[4 * j + 2] = v.z; fwr[4 * j + 3] = v.w;
            }
            p = (const float4*)(Wi + rowA * KDIM + h0 * KDIM + kb + segA);
#pragma unroll
            for (int j = 0; j < 4; j++) {
                float4 v = p[j];
                fwi[4 * j] = v.x; fwi[4 * j + 1] = v.y; fwi[4 * j + 2] = v.z; fwi[4 * j + 3] = v.w;
            }
            if (t < 128) {
                p = (const float4*)(g_zr + rowZ * KDIM + kb + segZ);
#pragma unroll
                for (int j = 0; j < 4; j++) {
                    float4 v = p[j];
                    fzr[4 * j] = v.x; fzr[4 * j + 1] = v.y; fzr[4 * j + 2] = v.z; fzr[4 * j + 3] = v.w;
                }
                p = (const float4*)(g_zi + rowZ * KDIM + kb + segZ);
#pragma unroll
                for (int j = 0; j < 4; j++) {
                    float4 v = p[j];
                    fzi[4 * j] = v.x; fzi[4 * j + 1] = v.y; fzi[4 * j + 2] = v.z; fzi[4 * j + 3] = v.w;
                }
            }
        }
        __syncthreads();
        {
            uint32_t hv[8], lv[8];
            int basew = rowA * SA + segA;
#pragma unroll
            for (int j = 0; j < 8; j++) cvt_pair2(fwr[2 * j], fwr[2 * j + 1], hv[j], lv[j]);
            *(uint4*)&sm[OFF_WRH + basew]     = make_uint4(hv[0], hv[1], hv[2], hv[3]);
            *(uint4*)&sm[OFF_WRH + basew + 8] = make_uint4(hv[4], hv[5], hv[6], hv[7]);
            *(uint4*)&sm[OFF_WRL + basew]     = make_uint4(lv[0], lv[1], lv[2], lv[3]);
            *(uint4*)&sm[OFF_WRL + basew + 8] = make_uint4(lv[4], lv[5], lv[6], lv[7]);
#pragma unroll
            for (int j = 0; j < 8; j++) cvt_pair2(fwi[2 * j], fwi[2 * j + 1], hv[j], lv[j]);
            *(uint4*)&sm[OFF_WIH + basew]     = make_uint4(hv[0], hv[1], hv[2], hv[3]);
            *(uint4*)&sm[OFF_WIH + basew + 8] = make_uint4(hv[4], hv[5], hv[6], hv[7]);
            *(uint4*)&sm[OFF_WIL + basew]     = make_uint4(lv[0], lv[1], lv[2], lv[3]);
            *(uint4*)&sm[OFF_WIL + basew + 8] = make_uint4(lv[4], lv[5], lv[6], lv[7]);
#pragma unroll
            for (int j = 0; j < 8; j++) cvt_pair2(fwr[2 * j] + fwi[2 * j], fwr[2 * j + 1] + fwi[2 * j + 1], hv[j], lv[j]);
            *(uint4*)&sm[OFF_WSH + basew]     = make_uint4(hv[0], hv[1], hv[2], hv[3]);
            *(uint4*)&sm[OFF_WSH + basew + 8] = make_uint4(hv[4], hv[5], hv[6], hv[7]);
            *(uint4*)&sm[OFF_WSL + basew]     = make_uint4(lv[0], lv[1], lv[2], lv[3]);
            *(uint4*)&sm[OFF_WSL + basew + 8] = make_uint4(lv[4], lv[5], lv[6], lv[7]);
            if (t < 128) {
                int basez = rowZ * SA + segZ;
#pragma unroll
                for (int j = 0; j < 8; j++) cvt_pair2(fzr[2 * j], fzr[2 * j + 1], hv[j], lv[j]);
                *(uint4*)&sm[OFF_ZRH + basez]     = make_uint4(hv[0], hv[1], hv[2], hv[3]);
                *(uint4*)&sm[OFF_ZRH + basez + 8] = make_uint4(hv[4], hv[5], hv[6], hv[7]);
                *(uint4*)&sm[OFF_ZRL + basez]     = make_uint4(lv[0], lv[1], lv[2], lv[3]);
                *(uint4*)&sm[OFF_ZRL + basez + 8] = make_uint4(lv[4], lv[5], lv[6], lv[7]);
#pragma unroll
                for (int j = 0; j < 8; j++) cvt_pair2(fzi[2 * j], fzi[2 * j + 1], hv[j], lv[j]);
                *(uint4*)&sm[OFF_ZIH + basez]     = make_uint4(hv[0], hv[1], hv[2], hv[3]);
                *(uint4*)&sm[OFF_ZIH + basez + 8] = make_uint4(hv[4], hv[5], hv[6], hv[7]);
                *(uint4*)&sm[OFF_ZIL + basez]     = make_uint4(lv[0], lv[1], lv[2], lv[3]);
                *(uint4*)&sm[OFF_ZIL + basez + 8] = make_uint4(lv[4], lv[5], lv[6], lv[7]);
#pragma unroll
                for (int j = 0; j < 8; j++) cvt_pair2(fzr[2 * j] + fzi[2 * j], fzr[2 * j + 1] + fzi[2 * j + 1], hv[j], lv[j]);
                *(uint4*)&sm[OFF_ZSH + basez]     = make_uint4(hv[0], hv[1], hv[2], hv[3]);
                *(uint4*)&sm[OFF_ZSH + basez + 8] = make_uint4(hv[4], hv[5], hv[6], hv[7]);
                *(uint4*)&sm[OFF_ZSL + basez]     = make_uint4(lv[0], lv[1], lv[2], lv[3]);
                *(uint4*)&sm[OFF_ZSL + basez + 8] = make_uint4(lv[4], lv[5], lv[6], lv[7]);
            }
        }
        __syncthreads();
        const int r0 = wid * 16;
#pragma unroll
        for (int kk = 0; kk < FC1_KCH; kk += 16) {
            uint32_t awrh[4], awrl[4], awih[4], awil[4], awsh[4], awsl[4];
            int a00 = (r0 + rl) * SA + kk + 2 * q;
            int a10 = (r0 + rl + 8) * SA + kk + 2 * q;
#define LDA(dst, OFF) \
            dst[0] = *(const uint32_t*)&sm[OFF + a00]; \
            dst[1] = *(const uint32_t*)&sm[OFF + a10]; \
            dst[2] = *(const uint32_t*)&sm[OFF + a00 + 8]; \
            dst[3] = *(const uint32_t*)&sm[OFF + a10 + 8];
            LDA(awrh, OFF_WRH) LDA(awrl, OFF_WRL)
            LDA(awih, OFF_WIH) LDA(awil, OFF_WIL)
            LDA(awsh, OFF_WSH) LDA(awsl, OFF_WSL)
#undef LDA
#pragma unroll
            for (int nt = 0; nt < 8; nt++) {
                int b0 = (nt * 8 + rl) * SA + kk + 2 * q;
                uint32_t bzrh[2], bzrl[2], bzih[2], bzil[2], bzsh[2], bzsl[2];
                bzrh[0] = *(const uint32_t*)&sm[OFF_ZRH + b0];
                bzrh[1] = *(const uint32_t*)&sm[OFF_ZRH + b0 + 8];
                bzrl[0] = *(const uint32_t*)&sm[OFF_ZRL + b0];
                bzrl[1] = *(const uint32_t*)&sm[OFF_ZRL + b0 + 8];
                bzih[0] = *(const uint32_t*)&sm[OFF_ZIH + b0];
                bzih[1] = *(const uint32_t*)&sm[OFF_ZIH + b0 + 8];
                bzil[0] = *(const uint32_t*)&sm[OFF_ZIL + b0];
                bzil[1] = *(const uint32_t*)&sm[OFF_ZIL + b0 + 8];
                bzsh[0] = *(const uint32_t*)&sm[OFF_ZSH + b0];
                bzsh[1] = *(const uint32_t*)&sm[OFF_ZSH + b0 + 8];
                bzsl[0] = *(const uint32_t*)&sm[OFF_ZSL + b0];
                bzsl[1] = *(const uint32_t*)&sm[OFF_ZSL + b0 + 8];
                mma16816(P1[nt], awrh, bzrh);
                mma16816(P1[nt], awrh, bzrl);
                mma16816(P1[nt], awrl, bzrh);
                mma16816(P2[nt], awih, bzih);
                mma16816(P2[nt], awih, bzil);
                mma16816(P2[nt], awil, bzih);
                mma16816(P3[nt], awsh, bzsh);
                mma16816(P3[nt], awsh, bzsl);
                mma16816(P3[nt], awsl, bzsh);
            }
        }
    }
    const int hbase = h0 + wid * 16 + rl;
#pragma unroll
    for (int nt = 0; nt < 8; nt++) {
        int n = nt * 8 + 2 * q;
#pragma unroll
        for (int jj = 0; jj < 4; jj++) {
            int nn = n + (jj & 1);
            int hh = hbase + (jj >> 1) * 8;
            float urv = P1[nt][jj] - P2[nt][jj];
            float uiv = P3[nt][jj] - P1[nt][jj] - P2[nt][jj];
            atomicAdd(&g_accU[nn * HID + hh], urv);
            atomicAdd(&g_accU[BATCH * HID + nn * HID + hh], uiv);
        }
    }
}

// ---------------- 8: bias+relu+cat+heads fused; pre-zero g_dd for next call ----------------
__global__ __launch_bounds__(128) void k_head(const float* __restrict__ fbr,
                                              const float* __restrict__ fbi,
                                              const float* __restrict__ aw,
                                              const float* __restrict__ ab,
                                              const float* __restrict__ cw,
                                              const float* __restrict__ cb,
                                              float* __restrict__ out) {
    float4 z4 = make_float4(0.f, 0.f, 0.f, 0.f);
    for (int i = blockIdx.x * 128 + threadIdx.x; i < NNODE * 2 / 4; i += BATCH * 128)
        ((float4*)g_dd)[i] = z4;

    __shared__ float s[1024];
    int b = blockIdx.x;
    for (int h = threadIdx.x; h < 512; h += 128) {
        s[h]       = fmaxf(g_accU[b * HID + h] + fbr[h], 0.f);
        s[512 + h] = fmaxf(g_accU[BATCH * HID + b * HID + h] + fbi[h], 0.f);
    }
    __syncthreads();
    int warp = threadIdx.x >> 5, lane = threadIdx.x & 31;
    for (int o = warp; o < 33; o += 4) {
        const float* wrow = (o < 32) ? (aw + o * 1024) : cw;
        float acc = 0.f;
        for (int k = lane; k < 1024; k += 32) acc += s[k] * wrow[k];
#pragma unroll
        for (int off = 16; off; off >>= 1) acc += __shfl_down_sync(0xffffffffu, acc, off);
        if (lane == 0) {
            if (o < 32) out[b * 32 + o] = acc + ab[o];
            else        out[BATCH * 32 + b] = acc + cb[0];
        }
    }
}

// ---------------- launch ----------------
extern "C" void kernel_launch(void* const* d_in, const int* in_sizes, int n_in,
                              void* d_out, int out_size) {
    const float* xr   = (const float*)d_in[0];
    const float* xi   = (const float*)d_in[1];
    const float* ew   = (const float*)d_in[2];
    const float* c1wr = (const float*)d_in[3];
    const float* c1wi = (const float*)d_in[4];
    const float* c1br = (const float*)d_in[5];
    const float* c1bi = (const float*)d_in[6];
    const float* chw  = (const float*)d_in[7];
    const float* chb  = (const float*)d_in[8];
    const float* f1wr = (const float*)d_in[9];
    const float* f1wi = (const float*)d_in[10];
    const float* f1br = (const float*)d_in[11];
    const float* f1bi = (const float*)d_in[12];
    const float* cw   = (const float*)d_in[13];
    const float* cb   = (const float*)d_in[14];
    const float* aw   = (const float*)d_in[15];
    const float* ab   = (const float*)d_in[16];
    const int*   ei   = (const int*)d_in[17];
    const int* row = ei;
    const int* col = ei + NEDGE;
    float* out = (float*)d_out;

    cudaFuncSetAttribute(k_fc1_mma, cudaFuncAttributeMaxDynamicSharedMemorySize, FC1_SMEM_BYTES);

    k_convdeg<<<NEDGE / 256, 256>>>(xr, xi, c1wr, c1wi, c1br, c1bi, row, ew);
    k_scan<<<NNODE / 256, 256>>>();
    k_fill<<<NEDGE / 256, 256>>>(row, col, ew);
    k_gather<<<NQUAD / (8 * QPW), 256>>>(0);
    k_gather<<<NQUAD / (8 * QPW), 256>>>(1);
    k_cheb<<<NNODE / 256, 256>>>(chw, chb);
    k_fc1_mma<<<dim3(4, FC1_KS), 256, FC1_SMEM_BYTES>>>(f1wr, f1wi);
    k_head<<<BATCH, 128>>>(f1br, f1bi, aw, ab, cw, cb, out);
}

// round 15
// speedup vs baseline: 1.0237x; 1.0237x over previous
#include <cuda_runtime.h>
#include <cuda_bf16.h>
#include <cstdint>

#define NNODE 131072
#define NEDGE 2097152
#define BATCH 64
#define NPG   2048
#define KDIM  20480   // N * CS
#define HID   512
#define NPAD  (NEDGE + 3 * NNODE)   // 2490368 padded slots
#define NQUAD (NPAD / 4)            // 622592
#define QPW   8
#define XSTR  32

#define FLAG_A 0x40000000u
#define FLAG_P 0x80000000u
#define VMASK  0x3FFFFFFFu

// fc1 mma.sync config (Karatsuba: 3 real products)
#define FC1_KS    32
#define FC1_KBLK  640
#define FC1_KCH   32
#define FC1_NCH   20
#define SA        40
#define OFF_WRH   0
#define OFF_WRL   5120
#define OFF_WIH   10240
#define OFF_WIL   15360
#define OFF_WSH   20480
#define OFF_WSL   25600
#define OFF_ZRH   30720
#define OFF_ZRL   33280
#define OFF_ZIH   35840
#define OFF_ZIL   38400
#define OFF_ZSH   40960
#define OFF_ZSL   43520
#define FC1_SMEM_BYTES  (46080 * 2)   // 92160

// ---------------- scratch ----------------
__device__ __align__(16) double g_dd[NNODE];        // zeroed by PREVIOUS call's k_head
__device__ __align__(16) float g_deg[NNODE];
__device__ __align__(16) int   g_cursor[NNODE];
__device__ unsigned int g_state[512];
__device__ int g_totq;                              // live quad count (written by k_scan)
__device__ __align__(16) int2  g_ecw[NPAD];
__device__ __align__(16) int   g_trow[NQUAD];
__device__ __align__(128) float g_T0[NNODE * XSTR];
__device__ __align__(128) float g_B1[NNODE * XSTR];
__device__ __align__(128) float g_B2[NNODE * XSTR];
__device__ __align__(16) float g_zr[BATCH * KDIM];
__device__ __align__(16) float g_zi[BATCH * KDIM];
__device__ __align__(16) float g_accU[2 * BATCH * HID];

// ---------------- helpers ----------------
__device__ __forceinline__ void red4(float* p, float a, float b, float c, float d) {
    asm volatile("red.global.add.v4.f32 [%0], {%1,%2,%3,%4};"
                 :: "l"(p), "f"(a), "f"(b), "f"(c), "f"(d));
}
__device__ __forceinline__ void mma16816(float* d, const uint32_t* a, const uint32_t* b) {
    asm volatile("mma.sync.aligned.m16n8k16.row.col.f32.bf16.bf16.f32 "
                 "{%0,%1,%2,%3}, {%4,%5,%6,%7}, {%8,%9}, {%0,%1,%2,%3};"
                 : "+f"(d[0]), "+f"(d[1]), "+f"(d[2]), "+f"(d[3])
                 : "r"(a[0]), "r"(a[1]), "r"(a[2]), "r"(a[3]), "r"(b[0]), "r"(b[1]));
}
__device__ __forceinline__ void cvt_pair2(float a, float b, uint32_t& hi, uint32_t& lo) {
    uint32_t h;
    asm("cvt.rn.bf16x2.f32 %0, %1, %2;" : "=r"(h) : "f"(b), "f"(a));
    float fa = __uint_as_float(h << 16);
    float fb = __uint_as_float(h & 0xFFFF0000u);
    float la = a - fa, lb = b - fb;
    uint32_t l;
    asm("cvt.rn.bf16x2.f32 %0, %1, %2;" : "=r"(l) : "f"(lb), "f"(la));
    hi = h; lo = l;
}
__device__ __forceinline__ void warp_flush(float* S, int rcur, float4 acc, int lane) {
    acc.x += __shfl_xor_sync(0xffffffffu, acc.x, 8);
    acc.y += __shfl_xor_sync(0xffffffffu, acc.y, 8);
    acc.z += __shfl_xor_sync(0xffffffffu, acc.z, 8);
    acc.w += __shfl_xor_sync(0xffffffffu, acc.w, 8);
    acc.x += __shfl_xor_sync(0xffffffffu, acc.x, 16);
    acc.y += __shfl_xor_sync(0xffffffffu, acc.y, 16);
    acc.z += __shfl_xor_sync(0xffffffffu, acc.z, 16);
    acc.w += __shfl_xor_sync(0xffffffffu, acc.w, 16);
    if (lane < 5) red4(S + rcur * XSTR + lane * 4, acc.x, acc.y, acc.z, acc.w);
}

// ---------------- 1: fused conv1 + degcnt + meta-zero ----------------
__global__ __launch_bounds__(256) void k_convdeg(const float* __restrict__ xr,
                                                 const float* __restrict__ xi,
                                                 const float* __restrict__ wr,
                                                 const float* __restrict__ wi,
                                                 const float* __restrict__ br,
                                                 const float* __restrict__ bi,
                                                 const int* __restrict__ row,
                                                 const float* __restrict__ ew) {
    __shared__ float swr[100], swi[100], sbr[10], sbi[10];
    int t = threadIdx.x;
    int bid = blockIdx.x;
    int e = bid * 256 + t;
    if (bid < 512) {
        if (t < 100) { swr[t] = wr[t]; swi[t] = wi[t]; }
        if (t < 10)  { sbr[t] = br[t]; sbi[t] = bi[t]; }
    }
    if (e < NPAD / 2) ((int4*)g_ecw)[e] = make_int4(0, 0, 0, 0);
    if (e < NQUAD) g_trow[e] = e & (NNODE - 1);
    if (e < 512) g_state[e] = 0u;
    if (e < 2 * BATCH * HID) g_accU[e] = 0.f;
    atomicAdd(&g_dd[row[e]], 1048576.0 + (double)ew[e]);

    if (bid < 512) {
        __syncthreads();
        int n = e;
        float a[10], b_[10];
#pragma unroll
        for (int k = 0; k < 10; k++) { a[k] = xr[n * 10 + k]; b_[k] = xi[n * 10 + k]; }
        float* o = g_T0 + n * XSTR;
#pragma unroll
        for (int c = 0; c < 10; c++) {
            float yr = sbr[c], yi = sbi[c];
#pragma unroll
            for (int k = 0; k < 10; k++) {
                yr += a[k] * swr[c * 10 + k] - b_[k] * swi[c * 10 + k];
                yi += a[k] * swi[c * 10 + k] + b_[k] * swr[c * 10 + k];
            }
            o[c]      = fmaxf(yr, 0.f);
            o[10 + c] = fmaxf(yi, 0.f);
        }
        float4 z4 = make_float4(0.f, 0.f, 0.f, 0.f);
        float4* b1 = (float4*)(g_B1 + n * XSTR);
        float4* b2 = (float4*)(g_B2 + n * XSTR);
#pragma unroll
        for (int j = 0; j < 5; j++) { b1[j] = z4; b2[j] = z4; }
    }
}

// ---------------- 2: single-pass scan (decoupled lookback) + dinv + cursor + totq ----------------
__global__ __launch_bounds__(256) void k_scan() {
    __shared__ int s[256];
    __shared__ int sprefix;
    int t = threadIdx.x, b = blockIdx.x, i = b * 256 + t;
    double dv = g_dd[i];
    int cnt = (int)(dv * 9.5367431640625e-7);
    int v = (cnt + 3) & ~3;
    s[t] = v;
    __syncthreads();
#pragma unroll
    for (int off = 1; off < 256; off <<= 1) {
        int a = (t >= off) ? s[t - off] : 0;
        __syncthreads();
        s[t] += a;
        __syncthreads();
    }
    int incl = s[t];
    if (b == 0) {
        if (t == 255) {
            atomicExch(&g_state[0], FLAG_P | (unsigned)incl);
            sprefix = 0;
        }
    } else if (t >= 224) {
        int lane = t & 31;
        if (lane == 31) atomicExch(&g_state[b], FLAG_A | (unsigned)incl);
        __syncwarp();
        int sum = 0, j0 = b - 1, done = 0;
        while (!done) {
            int j = j0 - lane;
            unsigned st = FLAG_P;
            if (j >= 0) {
                do { st = atomicAdd(&g_state[j], 0u); } while (st == 0u);
            }
            unsigned pm = __ballot_sync(0xffffffffu, (st & FLAG_P) != 0u);
            if (pm == 0u) {
                int val = (int)(st & VMASK);
#pragma unroll
                for (int o = 16; o; o >>= 1) val += __shfl_xor_sync(0xffffffffu, val, o);
                sum += val;
                j0 -= 32;
            } else {
                int pl = __ffs(pm) - 1;
                int val = (lane <= pl) ? (int)(st & VMASK) : 0;
#pragma unroll
                for (int o = 16; o; o >>= 1) val += __shfl_xor_sync(0xffffffffu, val, o);
                sum += val;
                done = 1;
            }
        }
        if (lane == 31) {
            atomicExch(&g_state[b], FLAG_P | (unsigned)(sum + incl));
            sprefix = sum;
        }
    }
    __syncthreads();
    int rs = incl - v + sprefix;
    g_cursor[i] = rs;
    if (b == 511 && t == 255) g_totq = (incl + sprefix) >> 2;   // live quad count
    double se = dv - (double)cnt * 1048576.0;
    g_deg[i] = (cnt > 0) ? rsqrtf((float)se + 1e-6f) : 0.f;
}

// ---------------- 3: CSR fill ----------------
__global__ void k_fill(const int* __restrict__ row, const int* __restrict__ col,
                       const float* __restrict__ ew) {
    int e = blockIdx.x * 256 + threadIdx.x;
    int r = row[e], c = col[e];
    float w = ew[e] * g_deg[r] * g_deg[c];
    int pos = atomicAdd(&g_cursor[r], 1);
    g_ecw[pos] = make_int2(c, __float_as_int(w));
    if (!(pos & 3)) g_trow[pos >> 2] = r;
}

// ---------------- 4/5: cooperative 8-lane gather, QPW=8, two-wave, tail early-exit ----------------
__global__ __launch_bounds__(256) void k_gather(int phase) {
    const float* __restrict__ X = (phase == 0) ? g_T0 : g_B1;
    float* S = (phase == 0) ? g_B1 : g_B2;
    int warpId = (blockIdx.x * 256 + threadIdx.x) >> 5;
    int lane = threadIdx.x & 31;
    int eSub = lane >> 3;
    int j = lane & 7;
    int q0 = warpId * QPW;
    if (q0 >= g_totq) return;   // dead-tail quads: nothing to do

    int4 r03 = ((const int4*)g_trow)[q0 >> 2];
    int4 r47 = ((const int4*)g_trow)[(q0 >> 2) + 1];

    // wave A: meta + data (MLP=4)
    int2 mA[4];
#pragma unroll
    for (int k = 0; k < 4; k++) mA[k] = g_ecw[(q0 + k) * 4 + eSub];
    float4 v[4];
#pragma unroll
    for (int k = 0; k < 4; k++) {
        float4 tv = make_float4(0.f, 0.f, 0.f, 0.f);
        if (j < 5) tv = ((const float4*)X)[mA[k].x * 8 + j];
        v[k] = tv;
    }
    // wave B meta issued early (independent)
    int2 mB[4];
#pragma unroll
    for (int k = 0; k < 4; k++) mB[k] = g_ecw[(q0 + 4 + k) * 4 + eSub];

    int rA[4] = {r03.x, r03.y, r03.z, r03.w};
    int rB[4] = {r47.x, r47.y, r47.z, r47.w};

    float4 acc = make_float4(0.f, 0.f, 0.f, 0.f);
    int rcur = rA[0];
#pragma unroll
    for (int k = 0; k < 4; k++) {
        if (rA[k] != rcur) {   // warp-uniform
            warp_flush(S, rcur, acc, lane);
            acc = make_float4(0.f, 0.f, 0.f, 0.f);
            rcur = rA[k];
        }
        float w = __int_as_float(mA[k].y);
        acc.x += w * v[k].x;
        acc.y += w * v[k].y;
        acc.z += w * v[k].z;
        acc.w += w * v[k].w;
    }
    // wave B data: reuse v registers
#pragma unroll
    for (int k = 0; k < 4; k++) {
        float4 tv = make_float4(0.f, 0.f, 0.f, 0.f);
        if (j < 5) tv = ((const float4*)X)[mB[k].x * 8 + j];
        v[k] = tv;
    }
#pragma unroll
    for (int k = 0; k < 4; k++) {
        if (rB[k] != rcur) {
            warp_flush(S, rcur, acc, lane);
            acc = make_float4(0.f, 0.f, 0.f, 0.f);
            rcur = rB[k];
        }
        float w = __int_as_float(mB[k].y);
        acc.x += w * v[k].x;
        acc.y += w * v[k].y;
        acc.z += w * v[k].z;
        acc.w += w * v[k].w;
    }
    warp_flush(S, rcur, acc, lane);
}

// ---------------- 6: cheb combine ----------------
__global__ __launch_bounds__(256) void k_cheb(const float* __restrict__ cw,
                                              const float* __restrict__ cb) {
    __shared__ float scw[300], scb[10];
    int t = threadIdx.x;
    for (int i = t; i < 300; i += 256) scw[i] = cw[i];
    if (t < 10) scb[t] = cb[t];
    __syncthreads();
    int n = blockIdx.x * 256 + t;
    float t0[20], t1[20], t2[20];
#pragma unroll
    for (int j = 0; j < 20; j++) {
        float x0 = g_T0[n * XSTR + j];
        float s1 = g_B1[n * XSTR + j];
        float g2 = g_B2[n * XSTR + j];
        t0[j] = x0;
        t1[j] = x0 - s1;
        t2[j] = x0 - 4.f * s1 + 2.f * g2;
    }
    int b = n >> 11;
    int nl = n & (NPG - 1);
    int base = b * KDIM + nl * 10;
#pragma unroll
    for (int o = 0; o < 10; o++) {
        float ar = scb[o], ai = 0.f;
#pragma unroll
        for (int i2 = 0; i2 < 10; i2++) {
            float w0 = scw[i2 * 10 + o], w1 = scw[100 + i2 * 10 + o], w2 = scw[200 + i2 * 10 + o];
            ar += t0[i2] * w0 + t1[i2] * w1 + t2[i2] * w2;
            ai += t0[10 + i2] * w0 + t1[10 + i2] * w1 + t2[10 + i2] * w2;
        }
        g_zr[base + o] = fmaxf(ar, 0.f);
        g_zi[base + o] = fmaxf(ai, 0.f);
    }
}

// ---------------- 7: fc1 complex GEMM — Karatsuba split-bf16 mma.sync ----------------
__global__ __launch_bounds__(256, 1) void k_fc1_mma(const float* __restrict__ Wr,
                                                    const float* __restrict__ Wi) {
    extern __shared__ __align__(16) __nv_bfloat16 sm[];
    const int t = threadIdx.x;
    const int wid = t >> 5, lane = t & 31;
    const int q = lane & 3, rl = lane >> 2;
    const int h0 = blockIdx.x * 128;
    const int kb0 = blockIdx.y * FC1_KBLK;

    const int rowA = t >> 1;
    const int segA = (t & 1) * 16;
    const int rowZ = t >> 1;
    const int segZ = (t & 1) * 16;

    float P1[8][4], P2[8][4], P3[8][4];
#pragma unroll
    for (int n = 0; n < 8; n++)
#pragma unroll
        for (int j = 0; j < 4; j++) { P1[n][j] = 0.f; P2[n][j] = 0.f; P3[n][j] = 0.f; }

    for (int c = 0; c < FC1_NCH; c++) {
        const int kb = kb0 + c * FC1_KCH;
        float fwr[16], fwi[16], fzr[16], fzi[16];
        {
            const float4* p = (const float4*)(Wr + rowA * KDIM + h0 * KDIM + kb + segA);
#pragma unroll
            for (int j = 0; j < 4; j++) {
                float4 v = p[j];
                fwr[4 * j] = v.x; fwr[4 * j + 1] = v.y; fwr[4 * j + 2] = v.z; fwr[4 * j + 3] = v.w;
            }
            p = (const float4*)(Wi + rowA * KDIM + h0 * KDIM + kb + segA);
#pragma unroll
            for (int j = 0; j < 4; j++) {
                float4 v = p[j];
                fwi[4 * j] = v.x; fwi[4 * j + 1] = v.y; fwi[4 * j + 2] = v.z; fwi[4 * j + 3] = v.w;
            }
            if (t < 128) {
                p = (const float4*)(g_zr + rowZ * KDIM + kb + segZ);
#pragma unroll
                for (int j = 0; j < 4; j++) {
                    float4 v = p[j];
                    fzr[4 * j] = v.x; fzr[4 * j + 1] = v.y; fzr[4 * j + 2] = v.z; fzr[4 * j + 3] = v.w;
                }
                p = (const float4*)(g_zi + rowZ * KDIM + kb + segZ);
#pragma unroll
                for (int j = 0; j < 4; j++) {
                    float4 v = p[j];
                    fzi[4 * j] = v.x; fzi[4 * j + 1] = v.y; fzi[4 * j + 2] = v.z; fzi[4 * j + 3] = v.w;
                }
            }
        }
        __syncthreads();
        {
            uint32_t hv[8], lv[8];
            int basew = rowA * SA + segA;
#pragma unroll
            for (int j = 0; j < 8; j++) cvt_pair2(fwr[2 * j], fwr[2 * j + 1], hv[j], lv[j]);
            *(uint4*)&sm[OFF_WRH + basew]     = make_uint4(hv[0], hv[1], hv[2], hv[3]);
            *(uint4*)&sm[OFF_WRH + basew + 8] = make_uint4(hv[4], hv[5], hv[6], hv[7]);
            *(uint4*)&sm[OFF_WRL + basew]     = make_uint4(lv[0], lv[1], lv[2], lv[3]);
            *(uint4*)&sm[OFF_WRL + basew + 8] = make_uint4(lv[4], lv[5], lv[6], lv[7]);
#pragma unroll
            for (int j = 0; j < 8; j++) cvt_pair2(fwi[2 * j], fwi[2 * j + 1], hv[j], lv[j]);
            *(uint4*)&sm[OFF_WIH + basew]     = make_uint4(hv[0], hv[1], hv[2], hv[3]);
            *(uint4*)&sm[OFF_WIH + basew + 8] = make_uint4(hv[4], hv[5], hv[6], hv[7]);
            *(uint4*)&sm[OFF_WIL + basew]     = make_uint4(lv[0], lv[1], lv[2], lv[3]);
            *(uint4*)&sm[OFF_WIL + basew + 8] = make_uint4(lv[4], lv[5], lv[6], lv[7]);
#pragma unroll
            for (int j = 0; j < 8; j++) cvt_pair2(fwr[2 * j] + fwi[2 * j], fwr[2 * j + 1] + fwi[2 * j + 1], hv[j], lv[j]);
            *(uint4*)&sm[OFF_WSH + basew]     = make_uint4(hv[0], hv[1], hv[2], hv[3]);
            *(uint4*)&sm[OFF_WSH + basew + 8] = make_uint4(hv[4], hv[5], hv[6], hv[7]);
            *(uint4*)&sm[OFF_WSL + basew]     = make_uint4(lv[0], lv[1], lv[2], lv[3]);
            *(uint4*)&sm[OFF_WSL + basew + 8] = make_uint4(lv[4], lv[5], lv[6], lv[7]);
            if (t < 128) {
                int basez = rowZ * SA + segZ;
#pragma unroll
                for (int j = 0; j < 8; j++) cvt_pair2(fzr[2 * j], fzr[2 * j + 1], hv[j], lv[j]);
                *(uint4*)&sm[OFF_ZRH + basez]     = make_uint4(hv[0], hv[1], hv[2], hv[3]);
                *(uint4*)&sm[OFF_ZRH + basez + 8] = make_uint4(hv[4], hv[5], hv[6], hv[7]);
                *(uint4*)&sm[OFF_ZRL + basez]     = make_uint4(lv[0], lv[1], lv[2], lv[3]);
                *(uint4*)&sm[OFF_ZRL + basez + 8] = make_uint4(lv[4], lv[5], lv[6], lv[7]);
#pragma unroll
                for (int j = 0; j < 8; j++) cvt_pair2(fzi[2 * j], fzi[2 * j + 1], hv[j], lv[j]);
                *(uint4*)&sm[OFF_ZIH + basez]     = make_uint4(hv[0], hv[1], hv[2], hv[3]);
                *(uint4*)&sm[OFF_ZIH + basez + 8] = make_uint4(hv[4], hv[5], hv[6], hv[7]);
                *(uint4*)&sm[OFF_ZIL + basez]     = make_uint4(lv[0], lv[1], lv[2], lv[3]);
                *(uint4*)&sm[OFF_ZIL + basez + 8] = make_uint4(lv[4], lv[5], lv[6], lv[7]);
#pragma unroll
                for (int j = 0; j < 8; j++) cvt_pair2(fzr[2 * j] + fzi[2 * j], fzr[2 * j + 1] + fzi[2 * j + 1], hv[j], lv[j]);
                *(uint4*)&sm[OFF_ZSH + basez]     = make_uint4(hv[0], hv[1], hv[2], hv[3]);
                *(uint4*)&sm[OFF_ZSH + basez + 8] = make_uint4(hv[4], hv[5], hv[6], hv[7]);
                *(uint4*)&sm[OFF_ZSL + basez]     = make_uint4(lv[0], lv[1], lv[2], lv[3]);
                *(uint4*)&sm[OFF_ZSL + basez + 8] = make_uint4(lv[4], lv[5], lv[6], lv[7]);
            }
        }
        __syncthreads();
        const int r0 = wid * 16;
#pragma unroll
        for (int kk = 0; kk < FC1_KCH; kk += 16) {
            uint32_t awrh[4], awrl[4], awih[4], awil[4], awsh[4], awsl[4];
            int a00 = (r0 + rl) * SA + kk + 2 * q;
            int a10 = (r0 + rl + 8) * SA + kk + 2 * q;
#define LDA(dst, OFF) \
            dst[0] = *(const uint32_t*)&sm[OFF + a00]; \
            dst[1] = *(const uint32_t*)&sm[OFF + a10]; \
            dst[2] = *(const uint32_t*)&sm[OFF + a00 + 8]; \
            dst[3] = *(const uint32_t*)&sm[OFF + a10 + 8];
            LDA(awrh, OFF_WRH) LDA(awrl, OFF_WRL)
            LDA(awih, OFF_WIH) LDA(awil, OFF_WIL)
            LDA(awsh, OFF_WSH) LDA(awsl, OFF_WSL)
#undef LDA
#pragma unroll
            for (int nt = 0; nt < 8; nt++) {
                int b0 = (nt * 8 + rl) * SA + kk + 2 * q;
                uint32_t bzrh[2], bzrl[2], bzih[2], bzil[2], bzsh[2], bzsl[2];
                bzrh[0] = *(const uint32_t*)&sm[OFF_ZRH + b0];
                bzrh[1] = *(const uint32_t*)&sm[OFF_ZRH + b0 + 8];
                bzrl[0] = *(const uint32_t*)&sm[OFF_ZRL + b0];
                bzrl[1] = *(const uint32_t*)&sm[OFF_ZRL + b0 + 8];
                bzih[0] = *(const uint32_t*)&sm[OFF_ZIH + b0];
                bzih[1] = *(const uint32_t*)&sm[OFF_ZIH + b0 + 8];
                bzil[0] = *(const uint32_t*)&sm[OFF_ZIL + b0];
                bzil[1] = *(const uint32_t*)&sm[OFF_ZIL + b0 + 8];
                bzsh[0] = *(const uint32_t*)&sm[OFF_ZSH + b0];
                bzsh[1] = *(const uint32_t*)&sm[OFF_ZSH + b0 + 8];
                bzsl[0] = *(const uint32_t*)&sm[OFF_ZSL + b0];
                bzsl[1] = *(const uint32_t*)&sm[OFF_ZSL + b0 + 8];
                mma16816(P1[nt], awrh, bzrh);
                mma16816(P1[nt], awrh, bzrl);
                mma16816(P1[nt], awrl, bzrh);
                mma16816(P2[nt], awih, bzih);
                mma16816(P2[nt], awih, bzil);
                mma16816(P2[nt], awil, bzih);
                mma16816(P3[nt], awsh, bzsh);
                mma16816(P3[nt], awsh, bzsl);
                mma16816(P3[nt], awsl, bzsh);
            }
        }
    }
    const int hbase = h0 + wid * 16 + rl;
#pragma unroll
    for (int nt = 0; nt < 8; nt++) {
        int n = nt * 8 + 2 * q;
#pragma unroll
        for (int jj = 0; jj < 4; jj++) {
            int nn = n + (jj & 1);
            int hh = hbase + (jj >> 1) * 8;
            float urv = P1[nt][jj] - P2[nt][jj];
            float uiv = P3[nt][jj] - P1[nt][jj] - P2[nt][jj];
            atomicAdd(&g_accU[nn * HID + hh], urv);
            atomicAdd(&g_accU[BATCH * HID + nn * HID + hh], uiv);
        }
    }
}

// ---------------- 8: bias+relu+cat+heads fused; pre-zero g_dd for next call ----------------
__global__ __launch_bounds__(128) void k_head(const float* __restrict__ fbr,
                                              const float* __restrict__ fbi,
                                              const float* __restrict__ aw,
                                              const float* __restrict__ ab,
                                              const float* __restrict__ cw,
                                              const float* __restrict__ cb,
                                              float* __restrict__ out) {
    float4 z4 = make_float4(0.f, 0.f, 0.f, 0.f);
    for (int i = blockIdx.x * 128 + threadIdx.x; i < NNODE * 2 / 4; i += BATCH * 128)
        ((float4*)g_dd)[i] = z4;

    __shared__ float s[1024];
    int b = blockIdx.x;
    for (int h = threadIdx.x; h < 512; h += 128) {
        s[h]       = fmaxf(g_accU[b * HID + h] + fbr[h], 0.f);
        s[512 + h] = fmaxf(g_accU[BATCH * HID + b * HID + h] + fbi[h], 0.f);
    }
    __syncthreads();
    int warp = threadIdx.x >> 5, lane = threadIdx.x & 31;
    for (int o = warp; o < 33; o += 4) {
        const float* wrow = (o < 32) ? (aw + o * 1024) : cw;
        float acc = 0.f;
        for (int k = lane; k < 1024; k += 32) acc += s[k] * wrow[k];
#pragma unroll
        for (int off = 16; off; off >>= 1) acc += __shfl_down_sync(0xffffffffu, acc, off);
        if (lane == 0) {
            if (o < 32) out[b * 32 + o] = acc + ab[o];
            else        out[BATCH * 32 + b] = acc + cb[0];
        }
    }
}

// ---------------- launch ----------------
extern "C" void kernel_launch(void* const* d_in, const int* in_sizes, int n_in,
                              void* d_out, int out_size) {
    const float* xr   = (const float*)d_in[0];
    const float* xi   = (const float*)d_in[1];
    const float* ew   = (const float*)d_in[2];
    const float* c1wr = (const float*)d_in[3];
    const float* c1wi = (const float*)d_in[4];
    const float* c1br = (const float*)d_in[5];
    const float* c1bi = (const float*)d_in[6];
    const float* chw  = (const float*)d_in[7];
    const float* chb  = (const float*)d_in[8];
    const float* f1wr = (const float*)d_in[9];
    const float* f1wi = (const float*)d_in[10];
    const float* f1br = (const float*)d_in[11];
    const float* f1bi = (const float*)d_in[12];
    const float* cw   = (const float*)d_in[13];
    const float* cb   = (const float*)d_in[14];
    const float* aw   = (const float*)d_in[15];
    const float* ab   = (const float*)d_in[16];
    const int*   ei   = (const int*)d_in[17];
    const int* row = ei;
    const int* col = ei + NEDGE;
    float* out = (float*)d_out;

    cudaFuncSetAttribute(k_fc1_mma, cudaFuncAttributeMaxDynamicSharedMemorySize, FC1_SMEM_BYTES);

    k_convdeg<<<NEDGE / 256, 256>>>(xr, xi, c1wr, c1wi, c1br, c1bi, row, ew);
    k_scan<<<NNODE / 256, 256>>>();
    k_fill<<<NEDGE / 256, 256>>>(row, col, ew);
    k_gather<<<NQUAD / (8 * QPW), 256>>>(0);
    k_gather<<<NQUAD / (8 * QPW), 256>>>(1);
    k_cheb<<<NNODE / 256, 256>>>(chw, chb);
    k_fc1_mma<<<dim3(4, FC1_KS), 256, FC1_SMEM_BYTES>>>(f1wr, f1wi);
    k_head<<<BATCH, 128>>>(f1br, f1bi, aw, ab, cw, cb, out);
}